// round 1
// baseline (speedup 1.0000x reference)
#include <cuda_runtime.h>
#include <cuda_bf16.h>
#include <cstdint>

#define BDIM 1024
#define KDIM 2048
#define NDIM 4096

// Scratch (device globals — no allocation allowed)
__device__ __nv_bfloat16 g_xb[BDIM * KDIM];   // x in bf16, [1024][2048]
__device__ __nv_bfloat16 g_wb[NDIM * KDIM];   // protos in bf16, [4096][2048] (= transpose(W) flat)
__device__ float g_xsq[BDIM];
__device__ float g_psq[NDIM];

// ---------------------------------------------------------------------------
// Kernel 1: zero p_sq accumulator
// ---------------------------------------------------------------------------
__global__ void zero_psq_k() {
    int i = blockIdx.x * blockDim.x + threadIdx.x;
    if (i < NDIM) g_psq[i] = 0.0f;
}

// ---------------------------------------------------------------------------
// Kernel 2: pack x -> bf16, compute x_sq (fp32). 1 block per row, 256 threads.
// ---------------------------------------------------------------------------
__global__ void pack_x_k(const float* __restrict__ x) {
    int row = blockIdx.x;
    int t = threadIdx.x;
    const float4* xr = reinterpret_cast<const float4*>(x + (size_t)row * KDIM);
    float4 v0 = xr[t * 2];
    float4 v1 = xr[t * 2 + 1];
    float s = v0.x*v0.x + v0.y*v0.y + v0.z*v0.z + v0.w*v0.w
            + v1.x*v1.x + v1.y*v1.y + v1.z*v1.z + v1.w*v1.w;

    __nv_bfloat162 o0 = __floats2bfloat162_rn(v0.x, v0.y);
    __nv_bfloat162 o1 = __floats2bfloat162_rn(v0.z, v0.w);
    __nv_bfloat162 o2 = __floats2bfloat162_rn(v1.x, v1.y);
    __nv_bfloat162 o3 = __floats2bfloat162_rn(v1.z, v1.w);
    uint4 pk;
    pk.x = *reinterpret_cast<uint32_t*>(&o0);
    pk.y = *reinterpret_cast<uint32_t*>(&o1);
    pk.z = *reinterpret_cast<uint32_t*>(&o2);
    pk.w = *reinterpret_cast<uint32_t*>(&o3);
    reinterpret_cast<uint4*>(g_xb + (size_t)row * KDIM)[t] = pk;

    #pragma unroll
    for (int off = 16; off; off >>= 1) s += __shfl_xor_sync(0xffffffffu, s, off);
    __shared__ float ws[8];
    if ((t & 31) == 0) ws[t >> 5] = s;
    __syncthreads();
    if (t == 0) {
        float tot = 0.0f;
        #pragma unroll
        for (int j = 0; j < 8; j++) tot += ws[j];
        g_xsq[row] = tot;
    }
}

// ---------------------------------------------------------------------------
// Kernel 3: transpose W [4096,2048] fp32 -> Wt bf16 [2048][4096] (flat = protos
// [4096][2048]), fused p_sq partial sums.
// p_sq[2*c + h] = sum over W rows r in half h of W[r,c]^2.
// Grid: (2048/32, 4096/32), block (32,8).
// ---------------------------------------------------------------------------
__global__ void pack_w_k(const float* __restrict__ W) {
    __shared__ float tile[32][33];
    __shared__ float sqs[8][32];

    int c0 = blockIdx.x * 32;   // W column
    int r0 = blockIdx.y * 32;   // W row
    int tx = threadIdx.x, ty = threadIdx.y;

    float sq = 0.0f;
    #pragma unroll
    for (int i = 0; i < 4; i++) {
        float v = W[(size_t)(r0 + ty + i * 8) * KDIM + (c0 + tx)];
        tile[ty + i * 8][tx] = v;
        sq += v * v;
    }
    sqs[ty][tx] = sq;
    __syncthreads();

    if (ty == 0) {
        float tot = 0.0f;
        #pragma unroll
        for (int j = 0; j < 8; j++) tot += sqs[j][tx];
        int half = (r0 >= KDIM) ? 1 : 0;   // rows [0,2048) -> half 0, [2048,4096) -> half 1
        atomicAdd(&g_psq[2 * (c0 + tx) + half], tot);
    }

    // Wt[c][r] = W[r][c]; Wt flat is [2048][4096]
    #pragma unroll
    for (int i = 0; i < 4; i++) {
        int c = c0 + ty + i * 8;
        int r = r0 + tx;
        g_wb[(size_t)c * NDIM + r] = __float2bfloat16_rn(tile[tx][ty + i * 8]);
    }
}

// ---------------------------------------------------------------------------
// Kernel 4: GEMM  out[b,o] = 2*sum_k xb[b,k]*wb[o,k] - xsq[b] - psq[o] - bias[o]
// BM=128, BN=128, BK=32, 3-stage cp.async pipeline, 256 threads (8 warps 4Mx2N),
// warp tile 32x64, mma.sync.m16n8k16 bf16 -> fp32.
// smem rows padded to 40 bf16 (80B) -> conflict-free ldmatrix.
// ---------------------------------------------------------------------------
#define BK 32
#define STAGES 3
#define ASTRIDE 40                        // bf16 elems per smem row
#define ROWB (ASTRIDE * 2)                // 80 bytes
#define STAGE_BYTES (128 * ROWB)          // 10240 per operand per stage
#define SMEM_TOTAL (STAGES * STAGE_BYTES * 2)   // 61440

#define CP16(dst_u32, src_ptr) \
    asm volatile("cp.async.cg.shared.global [%0], [%1], 16;\n" :: "r"(dst_u32), "l"(src_ptr))
#define CP_COMMIT() asm volatile("cp.async.commit_group;\n" ::)
#define CP_WAIT1()  asm volatile("cp.async.wait_group 1;\n" ::)

#define LDSM_X4(r0, r1, r2, r3, addr) \
    asm volatile("ldmatrix.sync.aligned.m8n8.x4.shared.b16 {%0,%1,%2,%3}, [%4];\n" \
                 : "=r"(r0), "=r"(r1), "=r"(r2), "=r"(r3) : "r"(addr))

#define MMA16816(d, a, b) \
    asm volatile("mma.sync.aligned.m16n8k16.row.col.f32.bf16.bf16.f32 " \
                 "{%0,%1,%2,%3},{%4,%5,%6,%7},{%8,%9},{%0,%1,%2,%3};\n" \
                 : "+f"(d[0]), "+f"(d[1]), "+f"(d[2]), "+f"(d[3]) \
                 : "r"(a[0]), "r"(a[1]), "r"(a[2]), "r"(a[3]), "r"(b[0]), "r"(b[1]))

#define LOAD_STAGE(stage, k0) do {                                     \
    uint32_t sa_ = sA + (stage) * STAGE_BYTES + sOff;                  \
    uint32_t sb_ = sB + (stage) * STAGE_BYTES + sOff;                  \
    const __nv_bfloat16* ga_ = gA0 + (k0);                             \
    const __nv_bfloat16* gb_ = gB0 + (k0);                             \
    CP16(sa_, ga_);                                                    \
    CP16(sa_ + 64 * ROWB, ga_ + (size_t)64 * KDIM);                    \
    CP16(sb_, gb_);                                                    \
    CP16(sb_ + 64 * ROWB, gb_ + (size_t)64 * KDIM);                    \
} while (0)

__global__ void __launch_bounds__(256) gemm_k(const float* __restrict__ bias,
                                              float* __restrict__ out) {
    extern __shared__ __nv_bfloat16 smem[];
    uint32_t smemAddr = (uint32_t)__cvta_generic_to_shared(smem);
    const uint32_t sA = smemAddr;
    const uint32_t sB = smemAddr + STAGES * STAGE_BYTES;

    const int t = threadIdx.x;
    const int bm = blockIdx.y * 128;
    const int bn = blockIdx.x * 128;

    // loader mapping: thread t -> (row t/4, chunk t%4) and (row t/4 + 64, chunk t%4)
    const int lrow = t >> 2, lch = t & 3;
    const __nv_bfloat16* gA0 = g_xb + (size_t)(bm + lrow) * KDIM + lch * 8;
    const __nv_bfloat16* gB0 = g_wb + (size_t)(bn + lrow) * KDIM + lch * 8;
    const uint32_t sOff = lrow * ROWB + lch * 16;

    const int warp = t >> 5, lane = t & 31;
    const int wm = warp & 3;   // 0..3 along M (32 rows each)
    const int wn = warp >> 2;  // 0..1 along N (64 cols each)

    float acc[2][8][4] = {};

    // prologue: prefetch stages 0..1
    LOAD_STAGE(0, 0);
    CP_COMMIT();
    LOAD_STAGE(1, BK);
    CP_COMMIT();

    const int NK = KDIM / BK;   // 64
    for (int kt = 0; kt < NK; ++kt) {
        CP_WAIT1();
        __syncthreads();

        if (kt + 2 < NK) {
            LOAD_STAGE((kt + 2) % STAGES, (kt + 2) * BK);
        }
        CP_COMMIT();

        const uint32_t sAs = sA + (kt % STAGES) * STAGE_BYTES;
        const uint32_t sBs = sB + (kt % STAGES) * STAGE_BYTES;

        #pragma unroll
        for (int ks = 0; ks < 2; ++ks) {
            uint32_t a[2][4];
            #pragma unroll
            for (int mi = 0; mi < 2; ++mi) {
                uint32_t addr = sAs + (uint32_t)(wm * 32 + mi * 16 + (lane & 15)) * ROWB
                              + (uint32_t)(ks * 2 + (lane >> 4)) * 16;
                LDSM_X4(a[mi][0], a[mi][1], a[mi][2], a[mi][3], addr);
            }
            uint32_t b[8][2];
            #pragma unroll
            for (int nj = 0; nj < 4; ++nj) {
                uint32_t addr = sBs
                    + (uint32_t)(wn * 64 + nj * 16 + (lane & 7) + ((lane & 16) >> 1)) * ROWB
                    + (uint32_t)(ks * 2 + ((lane >> 3) & 1)) * 16;
                uint32_t r0, r1, r2, r3;
                LDSM_X4(r0, r1, r2, r3, addr);
                b[2 * nj][0] = r0; b[2 * nj][1] = r1;
                b[2 * nj + 1][0] = r2; b[2 * nj + 1][1] = r3;
            }
            #pragma unroll
            for (int mi = 0; mi < 2; ++mi)
                #pragma unroll
                for (int ni = 0; ni < 8; ++ni)
                    MMA16816(acc[mi][ni], a[mi], b[ni]);
        }
    }

    // epilogue: out = 2*acc - xsq[row] - psq[col] - bias[col]
    const int gid = lane >> 2, qid = lane & 3;
    #pragma unroll
    for (int mi = 0; mi < 2; ++mi) {
        int row0 = bm + wm * 32 + mi * 16 + gid;
        float xs0 = g_xsq[row0];
        float xs1 = g_xsq[row0 + 8];
        #pragma unroll
        for (int ni = 0; ni < 8; ++ni) {
            int col = bn + wn * 64 + ni * 8 + qid * 2;
            float pb0 = g_psq[col] + __ldg(&bias[col]);
            float pb1 = g_psq[col + 1] + __ldg(&bias[col + 1]);
            float2 v0, v1;
            v0.x = 2.0f * acc[mi][ni][0] - xs0 - pb0;
            v0.y = 2.0f * acc[mi][ni][1] - xs0 - pb1;
            v1.x = 2.0f * acc[mi][ni][2] - xs1 - pb0;
            v1.y = 2.0f * acc[mi][ni][3] - xs1 - pb1;
            *reinterpret_cast<float2*>(out + (size_t)row0 * NDIM + col) = v0;
            *reinterpret_cast<float2*>(out + (size_t)(row0 + 8) * NDIM + col) = v1;
        }
    }
}

// ---------------------------------------------------------------------------
extern "C" void kernel_launch(void* const* d_in, const int* in_sizes, int n_in,
                              void* d_out, int out_size) {
    const float* x    = (const float*)d_in[0];
    const float* W    = (const float*)d_in[1];
    const float* bias = (const float*)d_in[2];
    float* out = (float*)d_out;

    cudaFuncSetAttribute(gemm_k, cudaFuncAttributeMaxDynamicSharedMemorySize, SMEM_TOTAL);

    zero_psq_k<<<NDIM / 256, 256>>>();
    pack_x_k<<<BDIM, 256>>>(x);
    pack_w_k<<<dim3(KDIM / 32, NDIM / 32), dim3(32, 8)>>>(W);
    gemm_k<<<dim3(NDIM / 128, BDIM / 128), 256, SMEM_TOTAL>>>(bias, out);
}

// round 3
// speedup vs baseline: 1.2866x; 1.2866x over previous
#include <cuda_runtime.h>
#include <cuda_bf16.h>
#include <cstdint>

#define BDIM 1024
#define KDIM 2048
#define NDIM 4096

// Scratch (device globals — no allocation allowed)
__device__ __nv_bfloat16 g_xb[BDIM * KDIM];   // 2*x in bf16 [1024][2048]
__device__ __nv_bfloat16 g_wb[NDIM * KDIM];   // protos in bf16 [4096][2048]
__device__ float g_xsq[BDIM];
__device__ float g_psq[NDIM];

// ---------------------------------------------------------------------------
// Kernel 1: zero p_sq accumulator
// ---------------------------------------------------------------------------
__global__ void zero_psq_k() {
    int i = blockIdx.x * blockDim.x + threadIdx.x;
    if (i < NDIM) g_psq[i] = 0.0f;
}

// ---------------------------------------------------------------------------
// Kernel 2: pack 2*x -> bf16 (exact: exponent bump), x_sq in fp32.
// ---------------------------------------------------------------------------
__global__ void pack_x_k(const float* __restrict__ x) {
    int row = blockIdx.x;
    int t = threadIdx.x;
    const float4* xr = reinterpret_cast<const float4*>(x + (size_t)row * KDIM);
    float4 v0 = xr[t * 2];
    float4 v1 = xr[t * 2 + 1];
    float s = v0.x*v0.x + v0.y*v0.y + v0.z*v0.z + v0.w*v0.w
            + v1.x*v1.x + v1.y*v1.y + v1.z*v1.z + v1.w*v1.w;

    __nv_bfloat162 o0 = __floats2bfloat162_rn(2.f*v0.x, 2.f*v0.y);
    __nv_bfloat162 o1 = __floats2bfloat162_rn(2.f*v0.z, 2.f*v0.w);
    __nv_bfloat162 o2 = __floats2bfloat162_rn(2.f*v1.x, 2.f*v1.y);
    __nv_bfloat162 o3 = __floats2bfloat162_rn(2.f*v1.z, 2.f*v1.w);
    uint4 pk;
    pk.x = *reinterpret_cast<uint32_t*>(&o0);
    pk.y = *reinterpret_cast<uint32_t*>(&o1);
    pk.z = *reinterpret_cast<uint32_t*>(&o2);
    pk.w = *reinterpret_cast<uint32_t*>(&o3);
    reinterpret_cast<uint4*>(g_xb + (size_t)row * KDIM)[t] = pk;

    #pragma unroll
    for (int off = 16; off; off >>= 1) s += __shfl_xor_sync(0xffffffffu, s, off);
    __shared__ float ws[8];
    if ((t & 31) == 0) ws[t >> 5] = s;
    __syncthreads();
    if (t == 0) {
        float tot = 0.0f;
        #pragma unroll
        for (int j = 0; j < 8; j++) tot += ws[j];
        g_xsq[row] = tot;
    }
}

// ---------------------------------------------------------------------------
// Kernel 3: transpose W [4096,2048] fp32 -> protos bf16 [4096][2048]
// (flat(W^T) == flat(protos)), fused p_sq partial sums.
// ---------------------------------------------------------------------------
__global__ void pack_w_k(const float* __restrict__ W) {
    __shared__ float tile[32][33];
    __shared__ float sqs[8][32];

    int c0 = blockIdx.x * 32;   // W column
    int r0 = blockIdx.y * 32;   // W row
    int tx = threadIdx.x, ty = threadIdx.y;

    float sq = 0.0f;
    #pragma unroll
    for (int i = 0; i < 4; i++) {
        float v = W[(size_t)(r0 + ty + i * 8) * KDIM + (c0 + tx)];
        tile[ty + i * 8][tx] = v;
        sq += v * v;
    }
    sqs[ty][tx] = sq;
    __syncthreads();

    if (ty == 0) {
        float tot = 0.0f;
        #pragma unroll
        for (int j = 0; j < 8; j++) tot += sqs[j][tx];
        int half = (r0 >= KDIM) ? 1 : 0;
        atomicAdd(&g_psq[2 * (c0 + tx) + half], tot);
    }

    #pragma unroll
    for (int i = 0; i < 4; i++) {
        int c = c0 + ty + i * 8;
        int r = r0 + tx;
        g_wb[(size_t)c * NDIM + r] = __float2bfloat16_rn(tile[tx][ty + i * 8]);
    }
}

// ---------------------------------------------------------------------------
// Kernel 4: GEMM  out[b,o] = sum_k (2x)b[b,k]*wb[o,k] - xsq[b] - psq[o] - bias[o]
// BM=BN=128, BK=32, 4-stage cp.async, 128 threads (4 warps 2Mx2N),
// warp tile 64x64, mma.sync.m16n8k16 bf16->fp32.
// smem rows padded to 40 bf16 (80B) -> conflict-free ldmatrix.
// ---------------------------------------------------------------------------
#define BK 32
#define STAGES 4
#define ROWB 80                           // bytes per padded smem row
#define OP_BYTES (128 * ROWB)             // 10240 per operand per stage
#define SLOT_BYTES (2 * OP_BYTES)         // 20480
#define TILE_OFF 512                      // pbc[128] floats first
#define SMEM_TOTAL (TILE_OFF + STAGES * SLOT_BYTES)   // 82432

#define CP16(dst_u32, src_ptr) \
    asm volatile("cp.async.cg.shared.global [%0], [%1], 16;\n" :: "r"(dst_u32), "l"(src_ptr))
#define CP_COMMIT() asm volatile("cp.async.commit_group;\n" ::)

#define LDSM_X4(r0, r1, r2, r3, addr) \
    asm volatile("ldmatrix.sync.aligned.m8n8.x4.shared.b16 {%0,%1,%2,%3}, [%4];\n" \
                 : "=r"(r0), "=r"(r1), "=r"(r2), "=r"(r3) : "r"(addr))

#define MMA16816(d, a, b) \
    asm volatile("mma.sync.aligned.m16n8k16.row.col.f32.bf16.bf16.f32 " \
                 "{%0,%1,%2,%3},{%4,%5,%6,%7},{%8,%9},{%0,%1,%2,%3};\n" \
                 : "+f"(d[0]), "+f"(d[1]), "+f"(d[2]), "+f"(d[3]) \
                 : "r"(a[0]), "r"(a[1]), "r"(a[2]), "r"(a[3]), "r"(b[0]), "r"(b[1]))

__global__ void __launch_bounds__(128, 2) gemm_k(const float* __restrict__ bias,
                                                 float* __restrict__ out) {
    extern __shared__ char smem[];
    const uint32_t sb = (uint32_t)__cvta_generic_to_shared(smem);
    float* pbc = reinterpret_cast<float*>(smem);     // [128] psq+bias for block cols
    const uint32_t sT = sb + TILE_OFF;

    const int t = threadIdx.x;
    const int bm = blockIdx.y * 128;
    const int bn = blockIdx.x * 128;

    pbc[t] = g_psq[bn + t] + __ldg(&bias[bn + t]);

    const __nv_bfloat16* gA = g_xb + (size_t)bm * KDIM;
    const __nv_bfloat16* gB = g_wb + (size_t)bn * KDIM;

    // loader: per operand 512 16B-chunks (row=c>>2, col=c&3), 4 chunks/thread
    auto load_slot = [&](int slot, int k0) {
        uint32_t abase = sT + slot * SLOT_BYTES;
        uint32_t bbase = abase + OP_BYTES;
        #pragma unroll
        for (int i = 0; i < 4; i++) {
            int c = t + i * 128;
            int row = c >> 2, col = c & 3;
            uint32_t off = (uint32_t)(row * ROWB + col * 16);
            CP16(abase + off, gA + (size_t)row * KDIM + k0 + col * 8);
            CP16(bbase + off, gB + (size_t)row * KDIM + k0 + col * 8);
        }
    };

    const int warp = t >> 5, lane = t & 31;
    const int wm = warp & 1;   // 64 rows
    const int wn = warp >> 1;  // 64 cols

    // precomputed intra-tile ldmatrix offsets (stage-relative)
    const uint32_t aoff = (uint32_t)((wm * 64 + (lane & 15)) * ROWB + (lane >> 4) * 16);
    const uint32_t boff = (uint32_t)((wn * 64 + (lane & 7) + ((lane & 16) >> 1)) * ROWB
                                     + ((lane >> 3) & 1) * 16);

    float acc[4][8][4] = {};

    #pragma unroll
    for (int s = 0; s < STAGES - 1; s++) {
        load_slot(s, s * BK);
        CP_COMMIT();
    }

    const int NK = KDIM / BK;   // 64
    for (int kt = 0; kt < NK; ++kt) {
        asm volatile("cp.async.wait_group %0;\n" :: "n"(STAGES - 2));
        __syncthreads();

        if (kt + STAGES - 1 < NK) load_slot((kt + STAGES - 1) % STAGES, (kt + STAGES - 1) * BK);
        CP_COMMIT();

        const uint32_t sAs = sT + (kt % STAGES) * SLOT_BYTES;
        const uint32_t sBs = sAs + OP_BYTES;

        #pragma unroll
        for (int ks = 0; ks < 2; ++ks) {
            uint32_t a[4][4];
            #pragma unroll
            for (int mi = 0; mi < 4; ++mi) {
                uint32_t addr = sAs + aoff + (uint32_t)(mi * 16 * ROWB) + (uint32_t)(ks * 32);
                LDSM_X4(a[mi][0], a[mi][1], a[mi][2], a[mi][3], addr);
            }
            uint32_t b[8][2];
            #pragma unroll
            for (int nj = 0; nj < 4; ++nj) {
                uint32_t addr = sBs + boff + (uint32_t)(nj * 16 * ROWB) + (uint32_t)(ks * 32);
                uint32_t r0, r1, r2, r3;
                LDSM_X4(r0, r1, r2, r3, addr);
                b[2 * nj][0] = r0;     b[2 * nj][1] = r1;
                b[2 * nj + 1][0] = r2; b[2 * nj + 1][1] = r3;
            }
            #pragma unroll
            for (int mi = 0; mi < 4; ++mi)
                #pragma unroll
                for (int ni = 0; ni < 8; ++ni)
                    MMA16816(acc[mi][ni], a[mi], b[ni]);
        }
    }

    // epilogue: out = acc - xsq[row] - (psq+bias)[col]
    const int gid = lane >> 2, qid = lane & 3;
    #pragma unroll
    for (int mi = 0; mi < 4; ++mi) {
        int row0 = bm + wm * 64 + mi * 16 + gid;
        float xs0 = g_xsq[row0];
        float xs1 = g_xsq[row0 + 8];
        #pragma unroll
        for (int ni = 0; ni < 8; ++ni) {
            int lc = wn * 64 + ni * 8 + qid * 2;
            float pb0 = pbc[lc];
            float pb1 = pbc[lc + 1];
            float2 v0, v1;
            v0.x = acc[mi][ni][0] - xs0 - pb0;
            v0.y = acc[mi][ni][1] - xs0 - pb1;
            v1.x = acc[mi][ni][2] - xs1 - pb0;
            v1.y = acc[mi][ni][3] - xs1 - pb1;
            *reinterpret_cast<float2*>(out + (size_t)row0 * NDIM + bn + lc) = v0;
            *reinterpret_cast<float2*>(out + (size_t)(row0 + 8) * NDIM + bn + lc) = v1;
        }
    }
}

// ---------------------------------------------------------------------------
extern "C" void kernel_launch(void* const* d_in, const int* in_sizes, int n_in,
                              void* d_out, int out_size) {
    const float* x    = (const float*)d_in[0];
    const float* W    = (const float*)d_in[1];
    const float* bias = (const float*)d_in[2];
    float* out = (float*)d_out;

    cudaFuncSetAttribute(gemm_k, cudaFuncAttributeMaxDynamicSharedMemorySize, SMEM_TOTAL);

    zero_psq_k<<<NDIM / 256, 256>>>();
    pack_x_k<<<BDIM, 256>>>(x);
    pack_w_k<<<dim3(KDIM / 32, NDIM / 32), dim3(32, 8)>>>(W);
    gemm_k<<<dim3(NDIM / 128, BDIM / 128), 128, SMEM_TOTAL>>>(bias, out);
}

// round 4
// speedup vs baseline: 1.3889x; 1.0795x over previous
#include <cuda_runtime.h>
#include <cuda_bf16.h>
#include <cstdint>

#define BDIM 1024
#define KDIM 2048
#define NDIM 4096

// Scratch (device globals — no allocation allowed)
__device__ __nv_bfloat16 g_xb[BDIM * KDIM];   // 2*x in bf16 [1024][2048]
__device__ __nv_bfloat16 g_wb[NDIM * KDIM];   // protos in bf16 [4096][2048]
__device__ float g_xsq[BDIM];
__device__ float g_psq[NDIM];

// ---------------------------------------------------------------------------
// Kernel 1: zero p_sq accumulator
// ---------------------------------------------------------------------------
__global__ void zero_psq_k() {
    int i = blockIdx.x * blockDim.x + threadIdx.x;
    if (i < NDIM) g_psq[i] = 0.0f;
}

// ---------------------------------------------------------------------------
// Kernel 2: pack 2*x -> bf16 (exact: exponent bump), x_sq in fp32.
// ---------------------------------------------------------------------------
__global__ void pack_x_k(const float* __restrict__ x) {
    int row = blockIdx.x;
    int t = threadIdx.x;
    const float4* xr = reinterpret_cast<const float4*>(x + (size_t)row * KDIM);
    float4 v0 = xr[t * 2];
    float4 v1 = xr[t * 2 + 1];
    float s = v0.x*v0.x + v0.y*v0.y + v0.z*v0.z + v0.w*v0.w
            + v1.x*v1.x + v1.y*v1.y + v1.z*v1.z + v1.w*v1.w;

    __nv_bfloat162 o0 = __floats2bfloat162_rn(2.f*v0.x, 2.f*v0.y);
    __nv_bfloat162 o1 = __floats2bfloat162_rn(2.f*v0.z, 2.f*v0.w);
    __nv_bfloat162 o2 = __floats2bfloat162_rn(2.f*v1.x, 2.f*v1.y);
    __nv_bfloat162 o3 = __floats2bfloat162_rn(2.f*v1.z, 2.f*v1.w);
    uint4 pk;
    pk.x = *reinterpret_cast<uint32_t*>(&o0);
    pk.y = *reinterpret_cast<uint32_t*>(&o1);
    pk.z = *reinterpret_cast<uint32_t*>(&o2);
    pk.w = *reinterpret_cast<uint32_t*>(&o3);
    reinterpret_cast<uint4*>(g_xb + (size_t)row * KDIM)[t] = pk;

    #pragma unroll
    for (int off = 16; off; off >>= 1) s += __shfl_xor_sync(0xffffffffu, s, off);
    __shared__ float ws[8];
    if ((t & 31) == 0) ws[t >> 5] = s;
    __syncthreads();
    if (t == 0) {
        float tot = 0.0f;
        #pragma unroll
        for (int j = 0; j < 8; j++) tot += ws[j];
        g_xsq[row] = tot;
    }
}

// ---------------------------------------------------------------------------
// Kernel 3: transpose W [4096,2048] fp32 -> protos bf16 [4096][2048]
// (flat(W^T) == flat(protos)), fused p_sq partial sums.
// ---------------------------------------------------------------------------
__global__ void pack_w_k(const float* __restrict__ W) {
    __shared__ float tile[32][33];
    __shared__ float sqs[8][32];

    int c0 = blockIdx.x * 32;   // W column
    int r0 = blockIdx.y * 32;   // W row
    int tx = threadIdx.x, ty = threadIdx.y;

    float sq = 0.0f;
    #pragma unroll
    for (int i = 0; i < 4; i++) {
        float v = W[(size_t)(r0 + ty + i * 8) * KDIM + (c0 + tx)];
        tile[ty + i * 8][tx] = v;
        sq += v * v;
    }
    sqs[ty][tx] = sq;
    __syncthreads();

    if (ty == 0) {
        float tot = 0.0f;
        #pragma unroll
        for (int j = 0; j < 8; j++) tot += sqs[j][tx];
        int half = (r0 >= KDIM) ? 1 : 0;
        atomicAdd(&g_psq[2 * (c0 + tx) + half], tot);
    }

    #pragma unroll
    for (int i = 0; i < 4; i++) {
        int c = c0 + ty + i * 8;
        int r = r0 + tx;
        g_wb[(size_t)c * NDIM + r] = __float2bfloat16_rn(tile[tx][ty + i * 8]);
    }
}

// ---------------------------------------------------------------------------
// Kernel 4: GEMM  out[b,o] = sum_k (2x)b[b,k]*wb[o,k] - xsq[b] - psq[o] - bias[o]
// BM=128, BN=256, BK=32, 4-stage cp.async, 256 threads (8 warps, 2Mx4N),
// warp tile 64x64, register double-buffered fragments.
// ---------------------------------------------------------------------------
#define BK 32
#define STAGES 4
#define ROWB 80                            // bytes per padded smem row
#define A_BYTES (128 * ROWB)               // 10240
#define B_BYTES (256 * ROWB)               // 20480
#define SLOT_BYTES (A_BYTES + B_BYTES)     // 30720
#define TILE_OFF 1024                      // pbc[256] floats first
#define SMEM_TOTAL (TILE_OFF + STAGES * SLOT_BYTES)   // 123904

#define CP16(dst_u32, src_ptr) \
    asm volatile("cp.async.cg.shared.global [%0], [%1], 16;\n" :: "r"(dst_u32), "l"(src_ptr))
#define CP_COMMIT() asm volatile("cp.async.commit_group;\n" ::)
#define CP_WAIT2()  asm volatile("cp.async.wait_group 2;\n" ::)

#define LDSM_X4(r0, r1, r2, r3, addr) \
    asm volatile("ldmatrix.sync.aligned.m8n8.x4.shared.b16 {%0,%1,%2,%3}, [%4];\n" \
                 : "=r"(r0), "=r"(r1), "=r"(r2), "=r"(r3) : "r"(addr))

#define MMA16816(d, a, b) \
    asm volatile("mma.sync.aligned.m16n8k16.row.col.f32.bf16.bf16.f32 " \
                 "{%0,%1,%2,%3},{%4,%5,%6,%7},{%8,%9},{%0,%1,%2,%3};\n" \
                 : "+f"(d[0]), "+f"(d[1]), "+f"(d[2]), "+f"(d[3]) \
                 : "r"(a[0]), "r"(a[1]), "r"(a[2]), "r"(a[3]), "r"(b[0]), "r"(b[1]))

// load one fragment set (A 4x ldsm.x4, B 4x ldsm.x4) from a stage at k-half ks
#define LDSM_FRAGS(abuf, bbuf, sAs, sBs, ks) do {                              \
    _Pragma("unroll")                                                          \
    for (int mi = 0; mi < 4; ++mi) {                                           \
        uint32_t addr = (sAs) + aoff + (uint32_t)(mi * 16 * ROWB) + (uint32_t)((ks) * 32); \
        LDSM_X4((abuf)[mi][0], (abuf)[mi][1], (abuf)[mi][2], (abuf)[mi][3], addr); \
    }                                                                          \
    _Pragma("unroll")                                                          \
    for (int nj = 0; nj < 4; ++nj) {                                           \
        uint32_t addr = (sBs) + boff + (uint32_t)(nj * 16 * ROWB) + (uint32_t)((ks) * 32); \
        uint32_t r0, r1, r2, r3;                                               \
        LDSM_X4(r0, r1, r2, r3, addr);                                         \
        (bbuf)[2 * nj][0] = r0;     (bbuf)[2 * nj][1] = r1;                    \
        (bbuf)[2 * nj + 1][0] = r2; (bbuf)[2 * nj + 1][1] = r3;                \
    }                                                                          \
} while (0)

#define MMA_BLOCK(abuf, bbuf) do {                                             \
    _Pragma("unroll")                                                          \
    for (int mi = 0; mi < 4; ++mi)                                             \
        _Pragma("unroll")                                                      \
        for (int ni = 0; ni < 8; ++ni)                                         \
            MMA16816(acc[mi][ni], (abuf)[mi], (bbuf)[ni]);                     \
} while (0)

__global__ void __launch_bounds__(256, 1) gemm_k(const float* __restrict__ bias,
                                                 float* __restrict__ out) {
    extern __shared__ char smem[];
    const uint32_t sb = (uint32_t)__cvta_generic_to_shared(smem);
    float* pbc = reinterpret_cast<float*>(smem);     // [256] psq+bias for block cols
    const uint32_t sT = sb + TILE_OFF;

    const int t = threadIdx.x;
    const int bm = blockIdx.y * 128;
    const int bn = blockIdx.x * 256;

    pbc[t] = g_psq[bn + t] + __ldg(&bias[bn + t]);

    const __nv_bfloat16* gA = g_xb + (size_t)bm * KDIM;
    const __nv_bfloat16* gB = g_wb + (size_t)bn * KDIM;

    // loader: A 512 chunks (2/thread), B 1024 chunks (4/thread); row=c>>2, col=c&3
    auto load_slot = [&](int slot, int k0) {
        uint32_t abase = sT + slot * SLOT_BYTES;
        uint32_t bbase = abase + A_BYTES;
        #pragma unroll
        for (int i = 0; i < 2; i++) {
            int c = t + i * 256;
            int row = c >> 2, col = c & 3;
            CP16(abase + (uint32_t)(row * ROWB + col * 16),
                 gA + (size_t)row * KDIM + k0 + col * 8);
        }
        #pragma unroll
        for (int i = 0; i < 4; i++) {
            int c = t + i * 256;
            int row = c >> 2, col = c & 3;
            CP16(bbase + (uint32_t)(row * ROWB + col * 16),
                 gB + (size_t)row * KDIM + k0 + col * 8);
        }
    };

    const int warp = t >> 5, lane = t & 31;
    const int wm = warp & 1;   // 2 x 64 rows
    const int wn = warp >> 1;  // 4 x 64 cols

    const uint32_t aoff = (uint32_t)((wm * 64 + (lane & 15)) * ROWB + (lane >> 4) * 16);
    const uint32_t boff = (uint32_t)((wn * 64 + (lane & 7) + ((lane & 16) >> 1)) * ROWB
                                     + ((lane >> 3) & 1) * 16);

    float acc[4][8][4] = {};
    uint32_t afr[2][4][4];
    uint32_t bfr[2][8][2];

    #pragma unroll
    for (int s = 0; s < STAGES - 1; s++) {
        load_slot(s, s * BK);
        CP_COMMIT();
    }

    CP_WAIT2();
    __syncthreads();

    // preload fragments for (kt=0, ks=0)
    {
        const uint32_t sAs = sT, sBs = sT + A_BYTES;
        LDSM_FRAGS(afr[0], bfr[0], sAs, sBs, 0);
    }

    const int NK = KDIM / BK;   // 64
    for (int kt = 0; kt < NK; ++kt) {
        const uint32_t sAs = sT + (kt % STAGES) * SLOT_BYTES;
        const uint32_t sBs = sAs + A_BYTES;

        // prefetch second k-half fragments, then issue next-stage global loads
        LDSM_FRAGS(afr[1], bfr[1], sAs, sBs, 1);
        if (kt + STAGES - 1 < NK) load_slot((kt + STAGES - 1) % STAGES, (kt + STAGES - 1) * BK);
        CP_COMMIT();

        MMA_BLOCK(afr[0], bfr[0]);

        if (kt + 1 < NK) {
            CP_WAIT2();
            __syncthreads();
            const uint32_t nAs = sT + ((kt + 1) % STAGES) * SLOT_BYTES;
            const uint32_t nBs = nAs + A_BYTES;
            LDSM_FRAGS(afr[0], bfr[0], nAs, nBs, 0);
        }

        MMA_BLOCK(afr[1], bfr[1]);
    }

    // epilogue: out = acc - xsq[row] - (psq+bias)[col]
    const int gid = lane >> 2, qid = lane & 3;
    #pragma unroll
    for (int mi = 0; mi < 4; ++mi) {
        int row0 = bm + wm * 64 + mi * 16 + gid;
        float xs0 = g_xsq[row0];
        float xs1 = g_xsq[row0 + 8];
        #pragma unroll
        for (int ni = 0; ni < 8; ++ni) {
            int lc = wn * 64 + ni * 8 + qid * 2;
            float pb0 = pbc[lc];
            float pb1 = pbc[lc + 1];
            float2 v0, v1;
            v0.x = acc[mi][ni][0] - xs0 - pb0;
            v0.y = acc[mi][ni][1] - xs0 - pb1;
            v1.x = acc[mi][ni][2] - xs1 - pb0;
            v1.y = acc[mi][ni][3] - xs1 - pb1;
            *reinterpret_cast<float2*>(out + (size_t)row0 * NDIM + bn + lc) = v0;
            *reinterpret_cast<float2*>(out + (size_t)(row0 + 8) * NDIM + bn + lc) = v1;
        }
    }
}

// ---------------------------------------------------------------------------
extern "C" void kernel_launch(void* const* d_in, const int* in_sizes, int n_in,
                              void* d_out, int out_size) {
    const float* x    = (const float*)d_in[0];
    const float* W    = (const float*)d_in[1];
    const float* bias = (const float*)d_in[2];
    float* out = (float*)d_out;

    cudaFuncSetAttribute(gemm_k, cudaFuncAttributeMaxDynamicSharedMemorySize, SMEM_TOTAL);

    zero_psq_k<<<NDIM / 256, 256>>>();
    pack_x_k<<<BDIM, 256>>>(x);
    pack_w_k<<<dim3(KDIM / 32, NDIM / 32), dim3(32, 8)>>>(W);
    gemm_k<<<dim3(NDIM / 256, BDIM / 128), 256, SMEM_TOTAL>>>(bias, out);
}